// round 17
// baseline (speedup 1.0000x reference)
#include <cuda_runtime.h>
#include <cstddef>

#define BSZ 8
#define SEQLEN 2048
#define VOCAB 32000
#define BOS 1
#define V4 (VOCAB / 4)               // 8000 float4 per row
#define FILL_BLOCKS (BSZ * SEQLEN)   // 16384 rows, one block each
#define THREADS 256
#define MAJ_THREADS 512              // one int4 (4 tokens) per thread
#define SMEM_HIST_BYTES (VOCAB * 4)  // 125 KB (sparsely used, lazily zeroed)

// Result scratch (allocation-free rule: __device__ globals only)
__device__ int g_pred[BSZ];

// ---------------------------------------------------------------------------
// Kernel A: per-batch majority, LAZY smem histogram:
//   1) each thread zeros hist[] only at its own tokens' slots (dups benign)
//   2) atomicAdd counts (spread ATOMS)
//   3) argmax = max over OCCURRING tokens of key=(cnt<<15)|(32767-v)
//      (reads only own tokens' final counts -- no vocab-wide scan)
// Untouched hist entries are never read. best=0 init -> BOS fallback when no
// valid tokens. Triggers PDL completion at entry.
// ---------------------------------------------------------------------------
__global__ __launch_bounds__(MAJ_THREADS) void majority_kernel(const int* __restrict__ ids) {
#if __CUDA_ARCH__ >= 900
    cudaTriggerProgrammaticLaunchCompletion();   // let fill grid launch now
#endif
    extern __shared__ int hist[];                // VOCAB ints, lazily zeroed
    const int b = blockIdx.x;
    const int t = threadIdx.x;

    __shared__ int best;
    if (t == 0) best = 0;

    // load this thread's 4 tokens (512 x LDG.128 covers SEQLEN=2048)
    const int4* row4 = (const int4*)(ids + (size_t)b * SEQLEN);
    int4 tk = row4[t];

    const bool vx = (tk.x != 0) && (tk.x != BOS);
    const bool vy = (tk.y != 0) && (tk.y != BOS);
    const bool vz = (tk.z != 0) && (tk.z != BOS);
    const bool vw = (tk.w != 0) && (tk.w != BOS);

    // 1) lazy zero: only slots that will be counted
    if (vx) hist[tk.x] = 0;
    if (vy) hist[tk.y] = 0;
    if (vz) hist[tk.z] = 0;
    if (vw) hist[tk.w] = 0;
    __syncthreads();

    // 2) count
    if (vx) atomicAdd(&hist[tk.x], 1);
    if (vy) atomicAdd(&hist[tk.y], 1);
    if (vz) atomicAdd(&hist[tk.z], 1);
    if (vw) atomicAdd(&hist[tk.w], 1);
    __syncthreads();

    // 3) argmax over occurring tokens only (final counts now stable)
    int lb = 0;
    if (vx) lb = max(lb, (hist[tk.x] << 15) | (32767 - tk.x));
    if (vy) lb = max(lb, (hist[tk.y] << 15) | (32767 - tk.y));
    if (vz) lb = max(lb, (hist[tk.z] << 15) | (32767 - tk.z));
    if (vw) lb = max(lb, (hist[tk.w] << 15) | (32767 - tk.w));
    atomicMax(&best, lb);
    __syncthreads();

    if (t == 0) {
        int cnt = best >> 15;
        int v = 32767 - (best & 32767);
        g_pred[b] = (cnt > 0) ? v : BOS;     // no valid tokens -> BOS
    }
}

// ---------------------------------------------------------------------------
// Kernel B (UNCHANGED from R8/R15 winner — proven 93.6% DRAM): streaming fill,
// one (b,s) row per block. Pure -6 STG.128 stream (no cache hints, no
// atomics, no fences), then HW-backed PDL wait, then thread 0 rewrites the
// aligned 32B sector holding the pred element (full-sector write, no RMW).
// ---------------------------------------------------------------------------
__global__ __launch_bounds__(THREADS) void fill_kernel(float4* __restrict__ out) {
    const int r = blockIdx.x;            // row index in [0, 16384)
    const int t = threadIdx.x;
    const int b = r >> 11;               // batch = r / SEQLEN

    const float4 neg = make_float4(-6.0f, -6.0f, -6.0f, -6.0f);
    float4* __restrict__ dst = out + (size_t)r * V4;

    for (int i = t; i < V4; i += THREADS) {
        dst[i] = neg;
    }

#if __CUDA_ARCH__ >= 900
    cudaGridDependencySynchronize();     // majority grid complete + visible
#endif
    __syncthreads();                     // order own -6 stores before patch

    if (t == 0) {
        const int p    = g_pred[b];
        const int base = p & ~7;         // 8-float (32B) aligned window
        const int c    = p & 7;

        float4 lo = neg, hi = neg;
        if      (c == 0) lo.x = 6.0f;
        else if (c == 1) lo.y = 6.0f;
        else if (c == 2) lo.z = 6.0f;
        else if (c == 3) lo.w = 6.0f;
        else if (c == 4) hi.x = 6.0f;
        else if (c == 5) hi.y = 6.0f;
        else if (c == 6) hi.z = 6.0f;
        else             hi.w = 6.0f;

        // row start (r * 128000B) and base*4 are 32B-aligned -> full sector
        float4* p4 = (float4*)((float*)dst + base);
        p4[0] = lo;
        p4[1] = hi;
    }
}

extern "C" void kernel_launch(void* const* d_in, const int* in_sizes, int n_in,
                              void* d_out, int out_size) {
    (void)in_sizes; (void)n_in; (void)out_size;
    const int* ids = (const int*)d_in[0];

    // raise dynamic smem limit for the 125 KB histogram (host attr set,
    // not a stream op — safe under graph capture; idempotent/deterministic)
    cudaFuncSetAttribute(majority_kernel,
                         cudaFuncAttributeMaxDynamicSharedMemorySize,
                         SMEM_HIST_BYTES);

    majority_kernel<<<BSZ, MAJ_THREADS, SMEM_HIST_BYTES>>>(ids);

    // Fill with programmatic dependent launch: overlaps with majority_kernel,
    // each block waits via cudaGridDependencySynchronize before patching.
    cudaLaunchConfig_t cfg = {};
    cfg.gridDim  = dim3(FILL_BLOCKS, 1, 1);
    cfg.blockDim = dim3(THREADS, 1, 1);
    cfg.dynamicSmemBytes = 0;
    cfg.stream = 0;   // same (legacy) stream the harness captures

    cudaLaunchAttribute attr[1];
    attr[0].id = cudaLaunchAttributeProgrammaticStreamSerialization;
    attr[0].val.programmaticStreamSerializationAllowed = 1;
    cfg.attrs = attr;
    cfg.numAttrs = 1;

    cudaLaunchKernelEx(&cfg, fill_kernel, (float4*)d_out);
}